// round 1
// baseline (speedup 1.0000x reference)
#include <cuda_runtime.h>

// ---------------------------------------------------------------------------
// MixingBlock: s = softmax((x Wq)(sl Wk)^T * scale) @ sl,  w = the softmax
// Shapes: x[4,8192,180], sl[4,32,1536], Wq[180,1536], Wk[1536,1536]
// Key restructure:  dots = x @ KQ^T with KQ[b,s,:180] = scale * (sl Wk) Wq^T
// ---------------------------------------------------------------------------

#define NB 4
#define NR 8192
#define NS 32
#define IN_DIM 180
#define SD 1536
#define AD 1536
#define BS (NB*NS)          // 128 (b,s) rows

#define KS 12               // K-split factor for P1
#define KCHUNK (SD/KS)      // 128

typedef unsigned long long ull;

__device__ float g_kpart[KS][BS][AD];   // partial k = sl @ Wk
__device__ float g_KQ[BS][IN_DIM];      // KQ (scale folded in)

// ---- packed f32x2 helpers -------------------------------------------------
__device__ __forceinline__ ull fpack(float x, float y) {
    ull r; asm("mov.b64 %0, {%1, %2};" : "=l"(r) : "f"(x), "f"(y)); return r;
}
__device__ __forceinline__ float2 funpack(ull v) {
    float2 r; asm("mov.b64 {%0, %1}, %2;" : "=f"(r.x), "=f"(r.y) : "l"(v)); return r;
}
__device__ __forceinline__ ull ffma2(ull a, ull b, ull c) {
    ull d; asm("fma.rn.f32x2 %0, %1, %2, %3;" : "=l"(d) : "l"(a), "l"(b), "l"(c)); return d;
}

// ---------------------------------------------------------------------------
// P1: k partials.  g_kpart[p][m][n] = sum_{d in chunk p} sl[m][d] * Wk[d][n]
// grid (24 n-tiles, 12 k-chunks), 256 threads. Thread tile: 4 m x 8 n (4 n-pairs)
// ---------------------------------------------------------------------------
__global__ __launch_bounds__(256) void p1_kernel(const float* __restrict__ sl,
                                                 const float* __restrict__ Wk) {
    const int n0 = blockIdx.x * 64;
    const int p  = blockIdx.y;
    const int d0 = p * KCHUNK;
    __shared__ float sSl[16][130];   // [dd][m], padded (conflict-light)
    __shared__ float sWk[16][64];    // [dd][n]
    const int tid = threadIdx.x;
    const int ng = tid & 7;          // n = n0 + ng*8 + {0..7}
    const int mg = tid >> 3;         // m = mg*4 + {0..3}

    ull acc[4][4];
    #pragma unroll
    for (int i = 0; i < 4; i++)
        #pragma unroll
        for (int q = 0; q < 4; q++) acc[i][q] = fpack(0.f, 0.f);

    for (int kk = 0; kk < KCHUNK; kk += 16) {
        __syncthreads();
        #pragma unroll
        for (int t = 0; t < 8; t++) {           // 16x128 sl tile (transposed)
            int idx = t * 256 + tid;
            int m = idx >> 4, dd = idx & 15;
            sSl[dd][m] = sl[m * SD + d0 + kk + dd];
        }
        #pragma unroll
        for (int t = 0; t < 4; t++) {           // 16x64 Wk tile
            int idx = t * 256 + tid;
            int dd = idx >> 6, n = idx & 63;
            sWk[dd][n] = Wk[(d0 + kk + dd) * AD + n0 + n];
        }
        __syncthreads();
        #pragma unroll
        for (int dd = 0; dd < 16; dd++) {
            ull a[4];
            #pragma unroll
            for (int q = 0; q < 4; q++)
                a[q] = *(const ull*)&sWk[dd][ng * 8 + 2 * q];
            #pragma unroll
            for (int i = 0; i < 4; i++) {
                float sv = sSl[dd][mg * 4 + i];
                ull sd = fpack(sv, sv);
                #pragma unroll
                for (int q = 0; q < 4; q++) acc[i][q] = ffma2(a[q], sd, acc[i][q]);
            }
        }
    }
    #pragma unroll
    for (int i = 0; i < 4; i++) {
        int m = mg * 4 + i;
        float* dst = &g_kpart[p][m][n0 + ng * 8];
        float2 v0 = funpack(acc[i][0]), v1 = funpack(acc[i][1]);
        float2 v2 = funpack(acc[i][2]), v3 = funpack(acc[i][3]);
        *(float4*)dst       = make_float4(v0.x, v0.y, v1.x, v1.y);
        *(float4*)(dst + 4) = make_float4(v2.x, v2.y, v3.x, v3.y);
    }
}

// ---------------------------------------------------------------------------
// P2: reduce k partials, compute KQ[m][j] = scale * sum_a k[m][a]*Wq[j][a]
// grid 64 blocks (2 (b,s)-rows each), 256 threads, warp-per-output.
// ---------------------------------------------------------------------------
__global__ __launch_bounds__(256) void p2_kernel(const float* __restrict__ Wq) {
    const int r0 = blockIdx.x * 2;
    __shared__ float ksm[2][SD];
    const int tid = threadIdx.x;

    for (int idx = tid; idx < 2 * SD; idx += 256) {
        int row = idx / SD, a = idx - row * SD;
        float accv = 0.f;
        #pragma unroll
        for (int p = 0; p < KS; p++) accv += g_kpart[p][r0 + row][a];
        ksm[row][a] = accv;
    }
    __syncthreads();

    const int wid = tid >> 5, lane = tid & 31;
    const float scale = rsqrtf((float)AD);
    for (int o = wid; o < 2 * IN_DIM; o += 8) {
        int row = (o >= IN_DIM) ? 1 : 0;
        int j = o - row * IN_DIM;
        const float* wq = Wq + (size_t)j * AD;
        float4 a4 = make_float4(0.f, 0.f, 0.f, 0.f);
        for (int a = lane * 4; a < SD; a += 128) {
            float4 kv = *(const float4*)&ksm[row][a];
            float4 wv = *(const float4*)&wq[a];
            a4.x += kv.x * wv.x; a4.y += kv.y * wv.y;
            a4.z += kv.z * wv.z; a4.w += kv.w * wv.w;
        }
        float accv = (a4.x + a4.y) + (a4.z + a4.w);
        #pragma unroll
        for (int off = 16; off; off >>= 1)
            accv += __shfl_xor_sync(0xffffffffu, accv, off);
        if (lane == 0) g_KQ[r0 + row][j] = accv * scale;
    }
}

// ---------------------------------------------------------------------------
// C1: dots = x @ KQ^T, softmax over 32 slots, write w.
// grid 1024 (32 rows each), 128 threads. Thread tile: 2 rows x 4 slots.
// ---------------------------------------------------------------------------
#define C1_ROWS 32
__global__ __launch_bounds__(128) void c1_kernel(const float* __restrict__ x,
                                                 float* __restrict__ w_out) {
    const int row0 = blockIdx.x * C1_ROWS;        // global row in [0, 32768)
    const int b = row0 >> 13;
    __shared__ float xs[C1_ROWS][181];            // padded
    __shared__ float kqt[IN_DIM][34];             // transposed, padded
    const int tid = threadIdx.x;

    for (int idx = tid; idx < C1_ROWS * IN_DIM; idx += 128) {
        int r = idx / IN_DIM, j = idx - r * IN_DIM;
        xs[r][j] = x[(size_t)(row0 + r) * IN_DIM + j];
    }
    for (int idx = tid; idx < NS * IN_DIM; idx += 128) {
        int s = idx / IN_DIM, j = idx - s * IN_DIM;
        kqt[j][s] = g_KQ[b * NS + s][j];
    }
    __syncthreads();

    const int sg = tid & 7;    // slots sg*4 + {0..3}
    const int rg = tid >> 3;   // rows rg*2 + {0,1}
    ull acc[2][2];
    #pragma unroll
    for (int i = 0; i < 2; i++) { acc[i][0] = fpack(0.f, 0.f); acc[i][1] = fpack(0.f, 0.f); }

    #pragma unroll 4
    for (int j = 0; j < IN_DIM; j++) {
        ull k0 = *(const ull*)&kqt[j][sg * 4];
        ull k1 = *(const ull*)&kqt[j][sg * 4 + 2];
        #pragma unroll
        for (int i = 0; i < 2; i++) {
            float xv = xs[rg * 2 + i][j];
            ull xd = fpack(xv, xv);
            acc[i][0] = ffma2(k0, xd, acc[i][0]);
            acc[i][1] = ffma2(k1, xd, acc[i][1]);
        }
    }
    #pragma unroll
    for (int i = 0; i < 2; i++) {
        float2 d01 = funpack(acc[i][0]), d23 = funpack(acc[i][1]);
        float m = fmaxf(fmaxf(d01.x, d01.y), fmaxf(d23.x, d23.y));
        m = fmaxf(m, __shfl_xor_sync(0xffffffffu, m, 1));
        m = fmaxf(m, __shfl_xor_sync(0xffffffffu, m, 2));
        m = fmaxf(m, __shfl_xor_sync(0xffffffffu, m, 4));
        float e0 = __expf(d01.x - m), e1 = __expf(d01.y - m);
        float e2 = __expf(d23.x - m), e3 = __expf(d23.y - m);
        float sum = (e0 + e1) + (e2 + e3);
        sum += __shfl_xor_sync(0xffffffffu, sum, 1);
        sum += __shfl_xor_sync(0xffffffffu, sum, 2);
        sum += __shfl_xor_sync(0xffffffffu, sum, 4);
        float inv = 1.0f / sum;
        int r = row0 + rg * 2 + i;
        *(float4*)&w_out[(size_t)r * NS + sg * 4] =
            make_float4(e0 * inv, e1 * inv, e2 * inv, e3 * inv);
    }
}

// ---------------------------------------------------------------------------
// C2: s_out[r][d] = sum_s w[r][s] * sl[b][s][d]   (K=32 skinny GEMM)
// grid (12 d-tiles x 512 row-tiles), 256 threads. Thread tile: 4 rows x 8 d.
// ---------------------------------------------------------------------------
__global__ __launch_bounds__(256) void c2_kernel(const float* __restrict__ sl,
                                                 const float* __restrict__ w_in,
                                                 float* __restrict__ s_out) {
    const int d0   = blockIdx.x * 128;
    const int row0 = blockIdx.y * 64;
    const int b    = row0 >> 13;
    __shared__ float sls[NS][128];
    __shared__ float ws[64][33];      // padded
    const int tid = threadIdx.x;

    #pragma unroll
    for (int t = 0; t < 16; t++) {    // 32x128 sl slice
        int idx = t * 256 + tid;
        int s = idx >> 7, dl = idx & 127;
        sls[s][dl] = sl[(size_t)(b * NS + s) * SD + d0 + dl];
    }
    #pragma unroll
    for (int t = 0; t < 8; t++) {     // 64x32 w tile
        int idx = t * 256 + tid;
        ws[idx >> 5][idx & 31] = w_in[(size_t)row0 * NS + idx];
    }
    __syncthreads();

    const int dg = tid & 15;   // d = d0 + dg*8 + {0..7}
    const int rg = tid >> 4;   // rows rg*4 + {0..3}
    ull acc[4][4];
    #pragma unroll
    for (int i = 0; i < 4; i++)
        #pragma unroll
        for (int q = 0; q < 4; q++) acc[i][q] = fpack(0.f, 0.f);

    #pragma unroll 4
    for (int s = 0; s < NS; s++) {
        const ull* ap = (const ull*)&sls[s][dg * 8];
        ull A0 = ap[0], A1 = ap[1], A2 = ap[2], A3 = ap[3];
        #pragma unroll
        for (int i = 0; i < 4; i++) {
            float wv = ws[rg * 4 + i][s];
            ull wd = fpack(wv, wv);
            acc[i][0] = ffma2(A0, wd, acc[i][0]);
            acc[i][1] = ffma2(A1, wd, acc[i][1]);
            acc[i][2] = ffma2(A2, wd, acc[i][2]);
            acc[i][3] = ffma2(A3, wd, acc[i][3]);
        }
    }
    #pragma unroll
    for (int i = 0; i < 4; i++) {
        int r = row0 + rg * 4 + i;
        float* dst = s_out + (size_t)r * SD + d0 + dg * 8;
        float2 v0 = funpack(acc[i][0]), v1 = funpack(acc[i][1]);
        float2 v2 = funpack(acc[i][2]), v3 = funpack(acc[i][3]);
        *(float4*)dst       = make_float4(v0.x, v0.y, v1.x, v1.y);
        *(float4*)(dst + 4) = make_float4(v2.x, v2.y, v3.x, v3.y);
    }
}

// ---------------------------------------------------------------------------
extern "C" void kernel_launch(void* const* d_in, const int* in_sizes, int n_in,
                              void* d_out, int out_size) {
    const float* x  = (const float*)d_in[0];   // [4,8192,180]
    const float* sl = (const float*)d_in[1];   // [4,32,1536]
    const float* Wq = (const float*)d_in[2];   // [180,1536]
    const float* Wk = (const float*)d_in[3];   // [1536,1536]
    float* out   = (float*)d_out;
    float* s_out = out;                               // [4,8192,1536]
    float* w_out = out + (size_t)NB * NR * SD;        // [4,8192,32]

    p1_kernel<<<dim3(AD / 64, KS), 256>>>(sl, Wk);
    p2_kernel<<<BS / 2, 256>>>(Wq);
    c1_kernel<<<(NB * NR) / C1_ROWS, 128>>>(x, w_out);
    c2_kernel<<<dim3(SD / 128, (NB * NR) / 64), 256>>>(sl, w_out, s_out);
}

// round 2
// speedup vs baseline: 1.2399x; 1.2399x over previous
#include <cuda_runtime.h>

// ---------------------------------------------------------------------------
// MixingBlock: s = softmax((x Wq)(sl Wk)^T * scale) @ sl,  w = the softmax
// Restructure: dots = x @ KQ^T with KQ = scale * (sl Wk) Wq^T  (tiny [128,180])
// ---------------------------------------------------------------------------

#define NB 4
#define NR 8192
#define NS 32
#define IN_DIM 180
#define SD 1536
#define AD 1536
#define BS (NB*NS)          // 128
#define KS 12
#define KCHUNK (SD/KS)      // 128

typedef unsigned long long ull;

__device__ float g_kpart[KS][BS][AD];
__device__ float g_KQ[BS][IN_DIM];

// ---- packed f32x2 helpers -------------------------------------------------
__device__ __forceinline__ ull fpack(float x, float y) {
    ull r; asm("mov.b64 %0, {%1, %2};" : "=l"(r) : "f"(x), "f"(y)); return r;
}
__device__ __forceinline__ float2 funpack(ull v) {
    float2 r; asm("mov.b64 {%0, %1}, %2;" : "=f"(r.x), "=f"(r.y) : "l"(v)); return r;
}
__device__ __forceinline__ ull ffma2(ull a, ull b, ull c) {
    ull d; asm("fma.rn.f32x2 %0, %1, %2, %3;" : "=l"(d) : "l"(a), "l"(b), "l"(c)); return d;
}
__device__ __forceinline__ ull d2u(double d) { return __double_as_longlong(d); }
__device__ __forceinline__ double u2d(ull v) { return __longlong_as_double(v); }

// ---------------------------------------------------------------------------
// P1: g_kpart[p][m][n] = sum_{d in chunk p} sl[m][d] * Wk[d][n]
// grid (6 n-tiles, 2 m-tiles, 12 k-chunks), 256 thr.
// Block tile 64m x 256n. Warp = 8m x 256n; lane owns d-distinct float4 pairs.
// ---------------------------------------------------------------------------
__global__ __launch_bounds__(256, 2) void p1_kernel(const float* __restrict__ sl,
                                                    const float* __restrict__ Wk) {
    const int n0 = blockIdx.x * 256;
    const int m0 = blockIdx.y * 64;
    const int p  = blockIdx.z;
    const int d0 = p * KCHUNK;
    __shared__ float sWk[16][256];   // 16 KB
    __shared__ ull   sslp[16][65];   // splatted sl, padded (8.3 KB)
    const int tid  = threadIdx.x;
    const int warp = tid >> 5, lane = tid & 31;
    const int mbase = warp * 8;

    ull acc[8][4];
    #pragma unroll
    for (int i = 0; i < 8; i++)
        #pragma unroll
        for (int q = 0; q < 4; q++) acc[i][q] = 0ULL;

    for (int kk = 0; kk < KCHUNK; kk += 16) {
        __syncthreads();
        #pragma unroll
        for (int t = 0; t < 4; t++) {            // Wk tile 16x256
            int idx = t * 256 + tid;
            int dd = idx >> 6, nq = idx & 63;
            *(float4*)&sWk[dd][nq * 4] =
                *(const float4*)&Wk[(size_t)(d0 + kk + dd) * AD + n0 + nq * 4];
        }
        #pragma unroll
        for (int t = 0; t < 4; t++) {            // sl tile 16x64, splatted
            int idx = t * 256 + tid;
            int m = idx >> 4, dd = idx & 15;
            float v = sl[(size_t)(m0 + m) * SD + d0 + kk + dd];
            sslp[dd][m] = fpack(v, v);
        }
        __syncthreads();
        #pragma unroll
        for (int dd = 0; dd < 16; dd++) {
            double2 a01 = *(const double2*)&sWk[dd][lane * 4];
            double2 a23 = *(const double2*)&sWk[dd][128 + lane * 4];
            ull A0 = d2u(a01.x), A1 = d2u(a01.y), A2 = d2u(a23.x), A3 = d2u(a23.y);
            #pragma unroll
            for (int i = 0; i < 8; i++) {
                ull wv = sslp[dd][mbase + i];
                acc[i][0] = ffma2(A0, wv, acc[i][0]);
                acc[i][1] = ffma2(A1, wv, acc[i][1]);
                acc[i][2] = ffma2(A2, wv, acc[i][2]);
                acc[i][3] = ffma2(A3, wv, acc[i][3]);
            }
        }
    }
    #pragma unroll
    for (int i = 0; i < 8; i++) {
        int m = m0 + mbase + i;
        float* dst = &g_kpart[p][m][n0 + lane * 4];
        *(double2*)dst         = make_double2(u2d(acc[i][0]), u2d(acc[i][1]));
        *(double2*)(dst + 128) = make_double2(u2d(acc[i][2]), u2d(acc[i][3]));
    }
}

// ---------------------------------------------------------------------------
// P2: reduce partials, KQ[m][j] = scale * sum_a k[m][a]*Wq[j][a]
// ---------------------------------------------------------------------------
__global__ __launch_bounds__(256) void p2_kernel(const float* __restrict__ Wq) {
    const int r0 = blockIdx.x * 2;
    __shared__ float ksm[2][SD];
    const int tid = threadIdx.x;

    for (int idx = tid; idx < 2 * SD; idx += 256) {
        int row = idx / SD, a = idx - row * SD;
        float accv = 0.f;
        #pragma unroll
        for (int p = 0; p < KS; p++) accv += g_kpart[p][r0 + row][a];
        ksm[row][a] = accv;
    }
    __syncthreads();

    const int wid = tid >> 5, lane = tid & 31;
    const float scale = rsqrtf((float)AD);
    for (int o = wid; o < 2 * IN_DIM; o += 8) {
        int row = (o >= IN_DIM) ? 1 : 0;
        int j = o - row * IN_DIM;
        const float* wq = Wq + (size_t)j * AD;
        float4 a4 = make_float4(0.f, 0.f, 0.f, 0.f);
        for (int a = lane * 4; a < SD; a += 128) {
            float4 kv = *(const float4*)&ksm[row][a];
            float4 wv = *(const float4*)&wq[a];
            a4.x += kv.x * wv.x; a4.y += kv.y * wv.y;
            a4.z += kv.z * wv.z; a4.w += kv.w * wv.w;
        }
        float accv = (a4.x + a4.y) + (a4.z + a4.w);
        #pragma unroll
        for (int off = 16; off; off >>= 1)
            accv += __shfl_xor_sync(0xffffffffu, accv, off);
        if (lane == 0) g_KQ[r0 + row][j] = accv * scale;
    }
}

// ---------------------------------------------------------------------------
// C1: dots = x @ KQ^T (K=180), softmax over 32 slots, write w.
// grid 1024 (32 rows each), 128 thr. Thread: 2 rows x 4 slots (slot-pair vec).
// ---------------------------------------------------------------------------
#define C1_ROWS 32
__global__ __launch_bounds__(128) void c1_kernel(const float* __restrict__ x,
                                                 float* __restrict__ w_out) {
    const int row0 = blockIdx.x * C1_ROWS;
    const int b = row0 >> 13;
    __shared__ float xs[C1_ROWS][IN_DIM];     // 23 KB
    __shared__ float kqt[IN_DIM][32];         // 23 KB, [j][s]
    const int tid = threadIdx.x;

    for (int idx = tid; idx < C1_ROWS * 45; idx += 128) {   // float4 fill of x
        int r = idx / 45, q = idx - r * 45;
        *(float4*)&xs[r][q * 4] =
            *(const float4*)&x[(size_t)(row0 + r) * IN_DIM + q * 4];
    }
    for (int idx = tid; idx < NS * IN_DIM; idx += 128) {
        int j = idx >> 5, s = idx & 31;
        kqt[j][s] = g_KQ[b * NS + s][j];
    }
    __syncthreads();

    const int sg = tid & 7;     // slots sg*4 + {0..3}
    const int rp = tid >> 3;    // rows rp*2 + {0,1}
    ull acc[2][2] = {{0ULL, 0ULL}, {0ULL, 0ULL}};

    #pragma unroll 4
    for (int j = 0; j < IN_DIM; j++) {
        double2 kd = *(const double2*)&kqt[j][sg * 4];
        ull k0 = d2u(kd.x), k1 = d2u(kd.y);
        #pragma unroll
        for (int i = 0; i < 2; i++) {
            float xv = xs[rp * 2 + i][j];
            ull xd = fpack(xv, xv);
            acc[i][0] = ffma2(k0, xd, acc[i][0]);
            acc[i][1] = ffma2(k1, xd, acc[i][1]);
        }
    }
    #pragma unroll
    for (int i = 0; i < 2; i++) {
        float2 d01 = funpack(acc[i][0]), d23 = funpack(acc[i][1]);
        float m = fmaxf(fmaxf(d01.x, d01.y), fmaxf(d23.x, d23.y));
        m = fmaxf(m, __shfl_xor_sync(0xffffffffu, m, 1));
        m = fmaxf(m, __shfl_xor_sync(0xffffffffu, m, 2));
        m = fmaxf(m, __shfl_xor_sync(0xffffffffu, m, 4));
        float e0 = __expf(d01.x - m), e1 = __expf(d01.y - m);
        float e2 = __expf(d23.x - m), e3 = __expf(d23.y - m);
        float sum = (e0 + e1) + (e2 + e3);
        sum += __shfl_xor_sync(0xffffffffu, sum, 1);
        sum += __shfl_xor_sync(0xffffffffu, sum, 2);
        sum += __shfl_xor_sync(0xffffffffu, sum, 4);
        float inv = 1.0f / sum;
        int r = row0 + rp * 2 + i;
        *(float4*)&w_out[(size_t)r * NS + sg * 4] =
            make_float4(e0 * inv, e1 * inv, e2 * inv, e3 * inv);
    }
}

// ---------------------------------------------------------------------------
// C2: s_out[r][d] = sum_s w[r][s] * sl[b][s][d]   (K=32 skinny GEMM)
// grid (6 d-tiles x 1024 row-tiles), 128 thr. Block tile 32 rows x 256 d.
// Warp = 8 rows x 256 d, lane owns distinct float4 pairs; w pre-splatted.
// ---------------------------------------------------------------------------
__global__ __launch_bounds__(128, 4) void c2_kernel(const float* __restrict__ sl,
                                                    const float* __restrict__ w_in,
                                                    float* __restrict__ s_out) {
    const int d0   = blockIdx.x * 256;
    const int row0 = blockIdx.y * 32;
    const int b    = row0 >> 13;
    __shared__ float sls[NS][256];    // 32 KB
    __shared__ ull   wsp[32][NS];     // splatted w, 8 KB
    const int tid  = threadIdx.x;
    const int warp = tid >> 5, lane = tid & 31;
    const int rbase = warp * 8;

    #pragma unroll
    for (int t = 0; t < 16; t++) {    // 32 s x 256 d (float4)
        int idx = t * 128 + tid;
        int s = idx >> 6, dq = idx & 63;
        *(float4*)&sls[s][dq * 4] =
            *(const float4*)&sl[(size_t)(b * NS + s) * SD + d0 + dq * 4];
    }
    #pragma unroll
    for (int t = 0; t < 8; t++) {     // 32 rows x 32 s, splatted
        int idx = t * 128 + tid;
        int r = idx >> 5, s = idx & 31;
        float v = w_in[(size_t)(row0 + r) * NS + s];
        wsp[r][s] = fpack(v, v);
    }
    __syncthreads();

    ull acc[8][4];
    #pragma unroll
    for (int i = 0; i < 8; i++)
        #pragma unroll
        for (int q = 0; q < 4; q++) acc[i][q] = 0ULL;

    #pragma unroll 2
    for (int s = 0; s < NS; s++) {
        double2 a01 = *(const double2*)&sls[s][lane * 4];
        double2 a23 = *(const double2*)&sls[s][128 + lane * 4];
        ull A0 = d2u(a01.x), A1 = d2u(a01.y), A2 = d2u(a23.x), A3 = d2u(a23.y);
        #pragma unroll
        for (int i = 0; i < 8; i++) {
            ull wv = wsp[rbase + i][s];
            acc[i][0] = ffma2(A0, wv, acc[i][0]);
            acc[i][1] = ffma2(A1, wv, acc[i][1]);
            acc[i][2] = ffma2(A2, wv, acc[i][2]);
            acc[i][3] = ffma2(A3, wv, acc[i][3]);
        }
    }
    #pragma unroll
    for (int i = 0; i < 8; i++) {
        int r = row0 + rbase + i;
        float* dst = s_out + (size_t)r * SD + d0 + lane * 4;
        *(double2*)dst         = make_double2(u2d(acc[i][0]), u2d(acc[i][1]));
        *(double2*)(dst + 128) = make_double2(u2d(acc[i][2]), u2d(acc[i][3]));
    }
}

// ---------------------------------------------------------------------------
extern "C" void kernel_launch(void* const* d_in, const int* in_sizes, int n_in,
                              void* d_out, int out_size) {
    const float* x  = (const float*)d_in[0];   // [4,8192,180]
    const float* sl = (const float*)d_in[1];   // [4,32,1536]
    const float* Wq = (const float*)d_in[2];   // [180,1536]
    const float* Wk = (const float*)d_in[3];   // [1536,1536]
    float* out   = (float*)d_out;
    float* s_out = out;                               // [4,8192,1536]
    float* w_out = out + (size_t)NB * NR * SD;        // [4,8192,32]

    p1_kernel<<<dim3(AD / 256, BS / 64, KS), 256>>>(sl, Wk);
    p2_kernel<<<BS / 2, 256>>>(Wq);
    c1_kernel<<<(NB * NR) / C1_ROWS, 128>>>(x, w_out);
    c2_kernel<<<dim3(SD / 256, (NB * NR) / 32), 128>>>(sl, w_out, s_out);
}